// round 1
// baseline (speedup 1.0000x reference)
#include <cuda_runtime.h>
#include <cstdint>

typedef unsigned long long ull;

#define Dm 64
#define MAXN 100000
#define MAXNP 25000

// Scratch buffers (device globals; no allocation allowed)
__device__ float g_h[MAXN * Dm];
__device__ float g_skip[MAXN * Dm];
__device__ float g_M[MAXN * Dm];
__device__ float g_aggr[MAXN * Dm];
__device__ float g_F[MAXNP * Dm];
__device__ float g_P[MAXNP * Dm];

static constexpr int RPB = 256;   // rows (=threads) per block for MLP kernel
static constexpr int AST = 66;    // smem row stride (even for float2, low conflict)

__device__ __forceinline__ ull pack2(float v) {
    ull r; asm("mov.b64 %0, {%1, %1};" : "=l"(r) : "f"(v)); return r;
}
__device__ __forceinline__ float2 unpack2(ull a) {
    float2 r; asm("mov.b64 {%0, %1}, %2;" : "=f"(r.x), "=f"(r.y) : "l"(a)); return r;
}
__device__ __forceinline__ void ffma2(ull& acc, ull a, ull b) {
    asm("fma.rn.f32x2 %0, %1, %2, %0;" : "+l"(acc) : "l"(a), "l"(b));
}

// Stage RPB rows of width W (16 or 64) from global into smem (coalesced).
template <int W, bool GMAP>
__device__ __forceinline__ void stage_rows(float* As, const float* __restrict__ src,
                                           const int* __restrict__ gmap,
                                           int rbase, int n, int tid) {
    constexpr int LOGW = (W == 64) ? 6 : 4;
    for (int idx = tid; idx < RPB * W; idx += RPB) {
        int rr = idx >> LOGW;
        int cc = idx & (W - 1);
        int grow = rbase + rr;
        float v = 0.f;
        if (grow < n) {
            int srow = GMAP ? __ldg(gmap + grow) : grow;
            v = __ldg(src + (size_t)srow * W + cc);
        }
        As[rr * AST + cc] = v;
    }
}

// acc[j] covers output cols (2j, 2j+1). W-step accumulation, weights broadcast from smem.
template <int W>
__device__ __forceinline__ void accum(ull (&acc)[32], const float* rowp, const float* Wp) {
    for (int i = 0; i < W; i++) {
        ull vv = pack2(rowp[i]);
        const ull* wr = (const ull*)(Wp + i * 64);
#pragma unroll
        for (int j = 0; j < 32; j++) ffma2(acc[j], vv, wr[j]);
    }
}

// out[row] = relu(in[row] @ W1 + b1) @ W2 + b2 (+ skip[row])
// in = in0[gmap?] (width K0), optionally concat in1 (width 64).
template <int K0, bool CONCAT, int NOUT, bool GMAP, bool SKIP>
__global__ void __launch_bounds__(RPB)
mlp2_kernel(const float* __restrict__ in0, const float* __restrict__ in1,
            const int* __restrict__ gmap, const float* __restrict__ skipb,
            const float* __restrict__ W1, const float* __restrict__ b1,
            const float* __restrict__ W2, const float* __restrict__ b2,
            float* __restrict__ out, int n) {
    constexpr int K1 = K0 + (CONCAT ? 64 : 0);
    extern __shared__ float sm[];
    float* W1s = sm;                      // K1*64
    float* W2s = W1s + K1 * 64;           // 64*NOUT
    float* b1s = W2s + 64 * NOUT;         // 64
    float* b2s = b1s + 64;                // <=64
    float* As  = b2s + 64;                // RPB*AST

    const int tid = threadIdx.x;
    const int rbase = blockIdx.x * RPB;

    for (int i = tid; i < K1 * 64; i += RPB) W1s[i] = W1[i];
    for (int i = tid; i < 64 * NOUT; i += RPB) W2s[i] = W2[i];
    if (tid < 64) b1s[tid] = b1[tid];
    if (tid < NOUT) b2s[tid] = b2[tid];

    stage_rows<K0, GMAP>(As, in0, gmap, rbase, n, tid);
    __syncthreads();

    ull acc[32];
    const ull* b1p = (const ull*)b1s;
#pragma unroll
    for (int j = 0; j < 32; j++) acc[j] = b1p[j];

    accum<K0>(acc, As + tid * AST, W1s);

    if (CONCAT) {
        __syncthreads();
        stage_rows<64, false>(As, in1, nullptr, rbase, n, tid);
        __syncthreads();
        accum<64>(acc, As + tid * AST, W1s + 64 * 64);
    }

    // relu -> hidden row back into smem
    __syncthreads();
    {
        float2* dst = (float2*)(As + tid * AST);
#pragma unroll
        for (int j = 0; j < 32; j++) {
            float2 p = unpack2(acc[j]);
            p.x = fmaxf(p.x, 0.f);
            p.y = fmaxf(p.y, 0.f);
            dst[j] = p;
        }
    }
    __syncthreads();

    constexpr int NJ = NOUT / 2;
    ull acc2[NJ];
    const ull* b2p = (const ull*)b2s;
#pragma unroll
    for (int j = 0; j < NJ; j++) acc2[j] = b2p[j];

    const float* hidp = As + tid * AST;
    for (int k = 0; k < 64; k++) {
        ull vv = pack2(hidp[k]);
        const ull* wr = (const ull*)(W2s + k * NOUT);
#pragma unroll
        for (int j = 0; j < NJ; j++) ffma2(acc2[j], vv, wr[j]);
    }

    if constexpr (NOUT == 2) {
        int grow = rbase + tid;
        if (grow < n) *(float2*)(out + (size_t)grow * 2) = unpack2(acc2[0]);
    } else {
        __syncthreads();
        {
            float2* dst = (float2*)(As + tid * AST);
#pragma unroll
            for (int j = 0; j < NJ; j++) dst[j] = unpack2(acc2[j]);
        }
        __syncthreads();
        for (int idx = tid; idx < RPB * 64; idx += RPB) {
            int rr = idx >> 6, cc = idx & 63;
            int grow = rbase + rr;
            if (grow < n) {
                float v = As[rr * AST + cc];
                if (SKIP) v += skipb[(size_t)grow * 64 + cc];
                out[(size_t)grow * 64 + cc] = v;
            }
        }
    }
}

// aggr[r[e]] += M[(smap? smap[s[e]] : s[e])], rows of 64 floats, 16 threads/edge.
__global__ void scatter_kernel(const float* __restrict__ M, const int* __restrict__ s,
                               const int* __restrict__ r, const int* __restrict__ smap,
                               int E, int rmax, float* __restrict__ aggr) {
    int t = blockIdx.x * blockDim.x + threadIdx.x;
    int e = t >> 4;
    if (e >= E) return;
    int ri = __ldg(r + e);
    if (ri >= rmax) return;
    int si = __ldg(s + e);
    if (smap) si = __ldg(smap + si);
    int c = (t & 15) << 2;
    float4 v = *(const float4*)(M + (size_t)si * 64 + c);
    atomicAdd((float4*)(aggr + (size_t)ri * 64 + c), v);
}

// dst[j] = src[idx[j]] (rows of 64 floats)
__global__ void gather_kernel(const float* __restrict__ src, const int* __restrict__ idx,
                              int n, float* __restrict__ dst) {
    int t = blockIdx.x * blockDim.x + threadIdx.x;
    int j = t >> 4;
    if (j >= n) return;
    int c = (t & 15) << 2;
    *(float4*)(dst + (size_t)j * 64 + c) = *(const float4*)(src + (size_t)__ldg(idx + j) * 64 + c);
}

static inline size_t smem_bytes(int K1, int NOUT) {
    return (size_t)(K1 * 64 + 64 * NOUT + 64 + 64 + RPB * AST) * 4;
}

extern "C" void kernel_launch(void* const* d_in, const int* in_sizes, int n_in,
                              void* d_out, int out_size) {
    const float* x   = (const float*)d_in[0];
    const float* We1 = (const float*)d_in[1];
    const float* be1 = (const float*)d_in[2];
    const float* We2 = (const float*)d_in[3];
    const float* be2 = (const float*)d_in[4];
    const float* Wm1 = (const float*)d_in[5];
    const float* bm1 = (const float*)d_in[6];
    const float* Wm2 = (const float*)d_in[7];
    const float* bm2 = (const float*)d_in[8];
    const float* Wn1 = (const float*)d_in[9];
    const float* bn1 = (const float*)d_in[10];
    const float* Wn2 = (const float*)d_in[11];
    const float* bn2 = (const float*)d_in[12];
    const float* Wd1 = (const float*)d_in[13];
    const float* bd1 = (const float*)d_in[14];
    const float* Wd2 = (const float*)d_in[15];
    const float* bd2 = (const float*)d_in[16];
    const int* s_fine   = (const int*)d_in[17];
    const int* r_fine   = (const int*)d_in[18];
    const int* s_ds     = (const int*)d_in[19];
    const int* r_ds     = (const int*)d_in[20];
    const int* s_p      = (const int*)d_in[21];
    const int* r_p      = (const int*)d_in[22];
    const int* s_us     = (const int*)d_in[23];
    const int* r_us     = (const int*)d_in[24];
    const int* uppool   = (const int*)d_in[25];
    const int* downpool = (const int*)d_in[26];

    const int E   = in_sizes[17];
    const int EDS = in_sizes[19];
    const int EP  = in_sizes[21];
    const int EUS = in_sizes[23];
    const int N   = in_sizes[25];
    const int NP  = in_sizes[26];

    float *h, *skip, *M, *aggr, *F, *P;
    cudaGetSymbolAddress((void**)&h, g_h);
    cudaGetSymbolAddress((void**)&skip, g_skip);
    cudaGetSymbolAddress((void**)&M, g_M);
    cudaGetSymbolAddress((void**)&aggr, g_aggr);
    cudaGetSymbolAddress((void**)&F, g_F);
    cudaGetSymbolAddress((void**)&P, g_P);

    cudaFuncSetAttribute(mlp2_kernel<16, false, 64, false, false>,
                         cudaFuncAttributeMaxDynamicSharedMemorySize, (int)smem_bytes(16, 64));
    cudaFuncSetAttribute(mlp2_kernel<64, false, 64, false, false>,
                         cudaFuncAttributeMaxDynamicSharedMemorySize, (int)smem_bytes(64, 64));
    cudaFuncSetAttribute(mlp2_kernel<64, true, 64, false, false>,
                         cudaFuncAttributeMaxDynamicSharedMemorySize, (int)smem_bytes(128, 64));
    cudaFuncSetAttribute(mlp2_kernel<64, true, 64, true, false>,
                         cudaFuncAttributeMaxDynamicSharedMemorySize, (int)smem_bytes(128, 64));
    cudaFuncSetAttribute(mlp2_kernel<64, true, 64, false, true>,
                         cudaFuncAttributeMaxDynamicSharedMemorySize, (int)smem_bytes(128, 64));
    cudaFuncSetAttribute(mlp2_kernel<64, false, 2, false, false>,
                         cudaFuncAttributeMaxDynamicSharedMemorySize, (int)smem_bytes(64, 2));

    auto nb = [](int rows) { return (rows + RPB - 1) / RPB; };
    auto eb = [](int e)    { return (e * 16 + 255) / 256; };
    const size_t rowB = (size_t)Dm * 4;
    float* out = (float*)d_out;

    // encode: h = mlp2(x)
    mlp2_kernel<16, false, 64, false, false><<<nb(N), RPB, smem_bytes(16, 64)>>>(
        x, nullptr, nullptr, nullptr, We1, be1, We2, be2, h, N);

    // L0, L1 (fine graph)
    for (int l = 0; l <= 1; l++) {
        mlp2_kernel<64, false, 64, false, false><<<nb(N), RPB, smem_bytes(64, 64)>>>(
            h, nullptr, nullptr, nullptr, Wm1 + l * 4096, bm1 + l * 64, Wm2 + l * 4096, bm2 + l * 64, M, N);
        cudaMemsetAsync(aggr, 0, (size_t)N * rowB);
        scatter_kernel<<<eb(E), 256>>>(M, s_fine, r_fine, nullptr, E, N, aggr);
        mlp2_kernel<64, true, 64, false, false><<<nb(N), RPB, smem_bytes(128, 64)>>>(
            h, aggr, nullptr, nullptr, Wn1 + l * 8192, bn1 + l * 64, Wn2 + l * 4096, bn2 + l * 64, h, N);
    }
    cudaMemcpyAsync(skip, h, (size_t)N * rowB, cudaMemcpyDeviceToDevice);

    // L2: downsample graph. uppool/downpool values < NP, so only first NP rows matter.
    {
        const int l = 2;
        mlp2_kernel<64, false, 64, false, false><<<nb(NP), RPB, smem_bytes(64, 64)>>>(
            h, nullptr, nullptr, nullptr, Wm1 + l * 4096, bm1 + l * 64, Wm2 + l * 4096, bm2 + l * 64, M, NP);
        cudaMemsetAsync(aggr, 0, (size_t)NP * rowB);
        scatter_kernel<<<eb(EDS), 256>>>(M, s_ds, r_ds, uppool, EDS, NP, aggr);
        mlp2_kernel<64, true, 64, true, false><<<nb(NP), RPB, smem_bytes(128, 64)>>>(
            h, aggr, uppool, nullptr, Wn1 + l * 8192, bn1 + l * 64, Wn2 + l * 4096, bn2 + l * 64, F, NP);
        gather_kernel<<<eb(NP), 256>>>(F, downpool, NP, P);
    }

    // L3, L4 (pooled graph)
    for (int l = 3; l <= 4; l++) {
        mlp2_kernel<64, false, 64, false, false><<<nb(NP), RPB, smem_bytes(64, 64)>>>(
            P, nullptr, nullptr, nullptr, Wm1 + l * 4096, bm1 + l * 64, Wm2 + l * 4096, bm2 + l * 64, M, NP);
        cudaMemsetAsync(aggr, 0, (size_t)NP * rowB);
        scatter_kernel<<<eb(EP), 256>>>(M, s_p, r_p, nullptr, EP, NP, aggr);
        mlp2_kernel<64, true, 64, false, false><<<nb(NP), RPB, smem_bytes(128, 64)>>>(
            P, aggr, nullptr, nullptr, Wn1 + l * 8192, bn1 + l * 64, Wn2 + l * 4096, bn2 + l * 64, P, NP);
    }

    // L5: upsample graph
    {
        const int l = 5;
        mlp2_kernel<64, false, 64, false, false><<<nb(NP), RPB, smem_bytes(64, 64)>>>(
            P, nullptr, nullptr, nullptr, Wm1 + l * 4096, bm1 + l * 64, Wm2 + l * 4096, bm2 + l * 64, M, NP);
        cudaMemsetAsync(aggr, 0, (size_t)NP * rowB);
        scatter_kernel<<<eb(EUS), 256>>>(M, s_us, r_us, downpool, EUS, NP, aggr);
        mlp2_kernel<64, true, 64, true, false><<<nb(NP), RPB, smem_bytes(128, 64)>>>(
            P, aggr, downpool, nullptr, Wn1 + l * 8192, bn1 + l * 64, Wn2 + l * 4096, bn2 + l * 64, F, NP);
        gather_kernel<<<eb(N), 256>>>(F, uppool, N, h);
    }

    // L6, L7 (fine graph, + skip)
    for (int l = 6; l <= 7; l++) {
        mlp2_kernel<64, false, 64, false, false><<<nb(N), RPB, smem_bytes(64, 64)>>>(
            h, nullptr, nullptr, nullptr, Wm1 + l * 4096, bm1 + l * 64, Wm2 + l * 4096, bm2 + l * 64, M, N);
        cudaMemsetAsync(aggr, 0, (size_t)N * rowB);
        scatter_kernel<<<eb(E), 256>>>(M, s_fine, r_fine, nullptr, E, N, aggr);
        mlp2_kernel<64, true, 64, false, true><<<nb(N), RPB, smem_bytes(128, 64)>>>(
            h, aggr, nullptr, skip, Wn1 + l * 8192, bn1 + l * 64, Wn2 + l * 4096, bn2 + l * 64, h, N);
    }

    // decode
    mlp2_kernel<64, false, 2, false, false><<<nb(N), RPB, smem_bytes(64, 2)>>>(
        h, nullptr, nullptr, nullptr, Wd1, bd1, Wd2, bd2, out, N);
}